// round 6
// baseline (speedup 1.0000x reference)
#include <cuda_runtime.h>

// ---------------------------------------------------------------------------
// Problem constants
// ---------------------------------------------------------------------------
#define TT   512
#define BB   1024
#define IN1  80
#define NH1  100
#define NG1  400
#define NH2  50
#define NG2  200

typedef unsigned long long ull;

// ---------------------------------------------------------------------------
// Device scratch
// ---------------------------------------------------------------------------
__device__ __align__(16) float g_pre1[(size_t)BB * TT * NG1];   // [b][t][400]
__device__ __align__(16) float g_h1  [(size_t)BB * TT * NH1];   // [b][t][100]
__device__ __align__(16) float g_pre2[(size_t)BB * TT * NG2];   // [b][t][200]

// GEMM weights: [k][pair][2] floats, pairs padded (208 / 104), zero-filled
__device__ __align__(16) float g_w1p[IN1 * 208 * 2];
__device__ __align__(16) float g_w2p[NH1 * 104 * 2];
// LSTM recurrent weights: plain [k][g]
__device__ __align__(16) float g_whh1T[NH1 * NG1];
__device__ __align__(16) float g_whh2T[NH2 * NG2];
// Fused biases, zero-padded
__device__ __align__(16) float g_b1[512];
__device__ __align__(16) float g_b2[512];

// ---------------------------------------------------------------------------
// f32x2 helpers (FFMA2 via PTX fma.rn.f32x2; bit-exact vs scalar FFMA)
// ---------------------------------------------------------------------------
__device__ __forceinline__ ull ffma2(ull d, ull a, ull b) {
    asm("fma.rn.f32x2 %0, %1, %2, %0;" : "+l"(d) : "l"(a), "l"(b));
    return d;
}
__device__ __forceinline__ ull dup2(float x) {
    ull r; unsigned u = __float_as_uint(x);
    asm("mov.b64 %0, {%1, %1};" : "=l"(r) : "r"(u));
    return r;
}
__device__ __forceinline__ ull pk(float x, float y) {
    ull r;
    asm("mov.b64 %0, {%1, %2};" : "=l"(r) : "f"(x), "f"(y));
    return r;
}
__device__ __forceinline__ void upk(ull v, float& a, float& b) {
    unsigned lo, hi;
    asm("mov.b64 {%0, %1}, %2;" : "=r"(lo), "=r"(hi) : "l"(v));
    a = __uint_as_float(lo); b = __uint_as_float(hi);
}

// Accurate fast activations (~1e-6 rel; NOT tanh.approx)
__device__ __forceinline__ float sigm(float x) {
    return __fdividef(1.0f, 1.0f + __expf(-x));
}
__device__ __forceinline__ float tanh_f(float x) {
    return __fdividef(2.0f, 1.0f + __expf(-2.0f * x)) - 1.0f;
}

// ---------------------------------------------------------------------------
// prep
// ---------------------------------------------------------------------------
__global__ void prep_kernel(const float* __restrict__ Wih1, const float* __restrict__ Whh1,
                            const float* __restrict__ bih1, const float* __restrict__ bhh1,
                            const float* __restrict__ Wih2, const float* __restrict__ Whh2,
                            const float* __restrict__ bih2, const float* __restrict__ bhh2) {
    int tid = blockIdx.x * blockDim.x + threadIdx.x;
    int stride = gridDim.x * blockDim.x;

    for (int i = tid; i < IN1 * 208 * 2; i += stride) {
        int k = i / (208 * 2), g = i % (208 * 2);
        g_w1p[i] = (g < NG1) ? Wih1[g * IN1 + k] : 0.0f;
    }
    for (int i = tid; i < NH1 * 104 * 2; i += stride) {
        int k = i / (104 * 2), g = i % (104 * 2);
        g_w2p[i] = (g < NG2) ? Wih2[g * NH1 + k] : 0.0f;
    }
    for (int i = tid; i < NH1 * NG1; i += stride) { int k = i / NG1, g = i % NG1; g_whh1T[i] = Whh1[g * NH1 + k]; }
    for (int i = tid; i < NH2 * NG2; i += stride) { int k = i / NG2, g = i % NG2; g_whh2T[i] = Whh2[g * NH2 + k]; }
    for (int i = tid; i < 512; i += stride) {
        g_b1[i] = (i < NG1) ? bih1[i] + bhh1[i] : 0.0f;
        g_b2[i] = (i < NG2) ? bih2[i] + bhh2[i] : 0.0f;
    }
}

// ---------------------------------------------------------------------------
// GEMM: out[m][GR] = x[m][K] @ W + b.
// M=128 tile, panel = 52 pairs (blockIdx.y), 13 warps x 4 pairs, 2 CTAs/SM.
// Lane owns rows {2l,2l+1,64+2l,65+2l}. x tile layout [k2][rowpair 64][4]
// (2 rows x 2 k per float4): 2 coalesced LDS.128 per 2k. Weights: 2 broadcast
// LDS.128 per k (4 pairs). => 6-8 wf per 32 FFMA2 per warp: FMA-bound.
// ---------------------------------------------------------------------------
template<int K, int GR, int PADTOT>
__global__ __launch_bounds__(416, 2)
void gemm_kernel(const float* __restrict__ x, const float* __restrict__ wp,
                 const float* __restrict__ bias, float* __restrict__ out) {
    constexpr int PANP = 52;                 // pairs per panel
    extern __shared__ float sm[];
    ull*   swp = (ull*)sm;                   // [k][52] weight pairs
    float* sx  = sm + K * PANP * 2;          // [k2][64][4] x tile

    int tid  = threadIdx.x;
    int lane = tid & 31;
    int wi   = tid >> 5;
    int m0   = blockIdx.x * 128;
    int pb   = blockIdx.y * PANP;            // pair base in global pair space

    const ull* wpu = (const ull*)wp;
    for (int i = tid; i < K * PANP; i += 416) {
        int k = i / PANP, p = i - k * PANP;
        swp[i] = wpu[(size_t)k * (PADTOT / 2) + pb + p];
    }
    for (int i = tid; i < 128 * K; i += 416) {
        int r = i / K, k = i - r * K;
        sx[(k >> 1) * 256 + (r >> 1) * 4 + (r & 1) * 2 + (k & 1)] =
            x[(size_t)(m0 + r) * K + k];
    }
    __syncthreads();

    int p0 = wi * 4;                          // warp's 4 pairs within panel

    ull acc[4][4];
#pragma unroll
    for (int j = 0; j < 4; j++) {
        ull b = pk(bias[2 * (pb + p0 + j)], bias[2 * (pb + p0 + j) + 1]);
#pragma unroll
        for (int r = 0; r < 4; r++) acc[r][j] = b;
    }

    const float* sxa = sx + 4 * lane;
    const float* sxb = sx + 4 * (lane + 32);
    const ull*   wb  = swp + p0;

    for (int k2 = 0; k2 < K / 2; k2++) {
        float4 xa = *(const float4*)(sxa + k2 * 256);   // rows 2l,2l+1 @ k0,k1
        float4 xb = *(const float4*)(sxb + k2 * 256);   // rows 64+2l,65+2l
        {   // k = 2*k2
            const ull* w = wb + (2 * k2) * PANP;
            ulonglong2 w01 = *(const ulonglong2*)(w);
            ulonglong2 w23 = *(const ulonglong2*)(w + 2);
            ull d0 = dup2(xa.x), d1 = dup2(xa.z), d2 = dup2(xb.x), d3 = dup2(xb.z);
            acc[0][0] = ffma2(acc[0][0], d0, w01.x); acc[1][0] = ffma2(acc[1][0], d1, w01.x);
            acc[2][0] = ffma2(acc[2][0], d2, w01.x); acc[3][0] = ffma2(acc[3][0], d3, w01.x);
            acc[0][1] = ffma2(acc[0][1], d0, w01.y); acc[1][1] = ffma2(acc[1][1], d1, w01.y);
            acc[2][1] = ffma2(acc[2][1], d2, w01.y); acc[3][1] = ffma2(acc[3][1], d3, w01.y);
            acc[0][2] = ffma2(acc[0][2], d0, w23.x); acc[1][2] = ffma2(acc[1][2], d1, w23.x);
            acc[2][2] = ffma2(acc[2][2], d2, w23.x); acc[3][2] = ffma2(acc[3][2], d3, w23.x);
            acc[0][3] = ffma2(acc[0][3], d0, w23.y); acc[1][3] = ffma2(acc[1][3], d1, w23.y);
            acc[2][3] = ffma2(acc[2][3], d2, w23.y); acc[3][3] = ffma2(acc[3][3], d3, w23.y);
        }
        {   // k = 2*k2+1
            const ull* w = wb + (2 * k2 + 1) * PANP;
            ulonglong2 w01 = *(const ulonglong2*)(w);
            ulonglong2 w23 = *(const ulonglong2*)(w + 2);
            ull d0 = dup2(xa.y), d1 = dup2(xa.w), d2 = dup2(xb.y), d3 = dup2(xb.w);
            acc[0][0] = ffma2(acc[0][0], d0, w01.x); acc[1][0] = ffma2(acc[1][0], d1, w01.x);
            acc[2][0] = ffma2(acc[2][0], d2, w01.x); acc[3][0] = ffma2(acc[3][0], d3, w01.x);
            acc[0][1] = ffma2(acc[0][1], d0, w01.y); acc[1][1] = ffma2(acc[1][1], d1, w01.y);
            acc[2][1] = ffma2(acc[2][1], d2, w01.y); acc[3][1] = ffma2(acc[3][1], d3, w01.y);
            acc[0][2] = ffma2(acc[0][2], d0, w23.x); acc[1][2] = ffma2(acc[1][2], d1, w23.x);
            acc[2][2] = ffma2(acc[2][2], d2, w23.x); acc[3][2] = ffma2(acc[3][2], d3, w23.x);
            acc[0][3] = ffma2(acc[0][3], d0, w23.y); acc[1][3] = ffma2(acc[1][3], d1, w23.y);
            acc[2][3] = ffma2(acc[2][3], d2, w23.y); acc[3][3] = ffma2(acc[3][3], d3, w23.y);
        }
    }

    if (2 * (pb + p0) < GR) {                 // panel/pad boundary is warp-exact
        int rows[4] = {2 * lane, 2 * lane + 1, 64 + 2 * lane, 65 + 2 * lane};
#pragma unroll
        for (int r = 0; r < 4; r++) {
            float* o = out + (size_t)(m0 + rows[r]) * GR + 2 * (pb + p0);
            *(ulonglong2*)(o)     = make_ulonglong2(acc[r][0], acc[r][1]);
            *(ulonglong2*)(o + 4) = make_ulonglong2(acc[r][2], acc[r][3]);
        }
    }
}

// ---------------------------------------------------------------------------
// Persistent LSTM: 8 batch rows/CTA, 128 CTAs, k-split KSPLIT, PPT cols/thread.
// Gate: per k: 2 broadcast LDS.128 (h pairs from shp[k][12]) + 1 coalesced
//   LDS (w, PPT floats) + PPT dups + 4*PPT FFMA2.
// Partials: sgt[ks][row][G], coalesced STS/LDS. Each ks adds pre for its rows.
// ---------------------------------------------------------------------------
template<int H, int PPT, int KSPLIT, bool LAST_ONLY>
__global__ __launch_bounds__(416, 1)
void lstm_kernel(const float* __restrict__ pre, const float* __restrict__ whhT,
                 float* __restrict__ hout) {
    constexpr int G    = 4 * H;
    constexpr int NCOL = G / PPT;            // col-threads per k-split
    constexpr int NACT = NCOL * KSPLIT;      // active gate threads
    constexpr int KH   = H / KSPLIT;
    constexpr int RPK  = 8 / KSPLIT;         // pre rows owned per ks group
    constexpr int UPT  = 8 * H / NACT;       // update units per thread
    constexpr int RPH  = 12;                 // shp row pad (16B aligned)

    extern __shared__ float sm[];
    float* sw  = sm;                          // [H][G]
    float* sgt = sm + H * G;                  // [KSPLIT][8][G]
    float* shp = sgt + KSPLIT * 8 * G;        // [H][12]

    int tid = threadIdx.x;
    int b0  = blockIdx.x * 8;

    for (int i = tid; i < H * G; i += blockDim.x) sw[i] = whhT[i];
    for (int i = tid; i < H * RPH; i += blockDim.x) shp[i] = 0.0f;
    __syncthreads();

    bool gate = (tid < NACT);
    int ks = 0, cg = 0;
    if (gate) { ks = tid / NCOL; cg = tid - ks * NCOL; }
    int c0 = PPT * cg;
    int k0 = ks * KH;
    int rbase = ks * RPK;                     // pre rows rbase..rbase+RPK-1

    int uj = tid % H;
    int ur[UPT];
#pragma unroll
    for (int i = 0; i < UPT; i++) ur[i] = tid / H + i * (NACT / H);
    float cst[UPT];
#pragma unroll
    for (int i = 0; i < UPT; i++) cst[i] = 0.0f;

    float pv[RPK][PPT];
    if (gate) {
#pragma unroll
        for (int rr = 0; rr < RPK; rr++) {
            const float* src = pre + ((size_t)(b0 + rbase + rr) * TT) * G + c0;
            if (PPT == 4) { float4 v = *(const float4*)src; pv[rr][0]=v.x; pv[rr][1]=v.y; pv[rr][2]=v.z; pv[rr][3]=v.w; }
            else          { float2 v = *(const float2*)src; pv[rr][0]=v.x; pv[rr][1]=v.y; }
        }
    }

    for (int t = 0; t < TT; t++) {
        if (gate) {
            ull acc[4][PPT];
#pragma unroll
            for (int q = 0; q < 4; q++)
#pragma unroll
                for (int j = 0; j < PPT; j++) acc[q][j] = 0ULL;
            // add pre for owned rows (pairs fully owned: RPK even)
#pragma unroll
            for (int qq = 0; qq < RPK / 2; qq++)
#pragma unroll
                for (int j = 0; j < PPT; j++)
                    acc[rbase / 2 + qq][j] = pk(pv[2 * qq][j], pv[2 * qq + 1][j]);

            // prefetch next timestep's pre
            int tn = (t + 1 < TT) ? t + 1 : t;
#pragma unroll
            for (int rr = 0; rr < RPK; rr++) {
                const float* src = pre + ((size_t)(b0 + rbase + rr) * TT + tn) * G + c0;
                if (PPT == 4) { float4 v = *(const float4*)src; pv[rr][0]=v.x; pv[rr][1]=v.y; pv[rr][2]=v.z; pv[rr][3]=v.w; }
                else          { float2 v = *(const float2*)src; pv[rr][0]=v.x; pv[rr][1]=v.y; }
            }

#pragma unroll 2
            for (int k = k0; k < k0 + KH; k++) {
                ulonglong2 hA = *(const ulonglong2*)(shp + k * RPH);       // rows 0-3
                ulonglong2 hB = *(const ulonglong2*)(shp + k * RPH + 4);   // rows 4-7
                const float* wr = sw + k * G + c0;
                float wf[PPT];
                if (PPT == 4) { float4 v = *(const float4*)wr; wf[0]=v.x; wf[1]=v.y; wf[2]=v.z; wf[3]=v.w; }
                else          { float2 v = *(const float2*)wr; wf[0]=v.x; wf[1]=v.y; }
#pragma unroll
                for (int j = 0; j < PPT; j++) {
                    ull wd = dup2(wf[j]);
                    acc[0][j] = ffma2(acc[0][j], hA.x, wd);
                    acc[1][j] = ffma2(acc[1][j], hA.y, wd);
                    acc[2][j] = ffma2(acc[2][j], hB.x, wd);
                    acc[3][j] = ffma2(acc[3][j], hB.y, wd);
                }
            }

            // store partials: sgt[ks][row][c0..] coalesced
#pragma unroll
            for (int q = 0; q < 4; q++) {
                float lo[PPT], hi[PPT];
#pragma unroll
                for (int j = 0; j < PPT; j++) upk(acc[q][j], lo[j], hi[j]);
                float* r0p = sgt + (ks * 8 + 2 * q)     * G + c0;
                float* r1p = sgt + (ks * 8 + 2 * q + 1) * G + c0;
                if (PPT == 4) {
                    *(float4*)r0p = make_float4(lo[0], lo[1], lo[2], lo[3]);
                    *(float4*)r1p = make_float4(hi[0], hi[1], hi[2], hi[3]);
                } else {
                    *(float2*)r0p = make_float2(lo[0], lo[1]);
                    *(float2*)r1p = make_float2(hi[0], hi[1]);
                }
            }
        }
        __syncthreads();

        if (tid < NACT) {
#pragma unroll
            for (int i = 0; i < UPT; i++) {
                int r = ur[i];
                float gs[4];
#pragma unroll
                for (int gidx = 0; gidx < 4; gidx++) {
                    float s = 0.0f;
#pragma unroll
                    for (int k2 = 0; k2 < KSPLIT; k2++)
                        s += sgt[(k2 * 8 + r) * G + gidx * H + uj];
                    gs[gidx] = s;
                }
                float ig = sigm(gs[0]);
                float fg = sigm(gs[1]);
                float gv = tanh_f(gs[2]);
                float og = sigm(gs[3]);
                float c  = fg * cst[i] + ig * gv;
                cst[i] = c;
                float h  = og * tanh_f(c);
                shp[uj * RPH + r] = h;
                if (!LAST_ONLY) {
                    hout[((size_t)(b0 + r) * TT + t) * H + uj] = h;
                } else if (t == TT - 1) {
                    hout[(size_t)(b0 + r) * H + uj] = h;
                }
            }
        }
        __syncthreads();
    }
}

// ---------------------------------------------------------------------------
// Launch
// ---------------------------------------------------------------------------
extern "C" void kernel_launch(void* const* d_in, const int* in_sizes, int n_in,
                              void* d_out, int out_size) {
    const float* x    = (const float*)d_in[0];
    const float* Wih1 = (const float*)d_in[1];
    const float* Whh1 = (const float*)d_in[2];
    const float* bih1 = (const float*)d_in[3];
    const float* bhh1 = (const float*)d_in[4];
    const float* Wih2 = (const float*)d_in[5];
    const float* Whh2 = (const float*)d_in[6];
    const float* bih2 = (const float*)d_in[7];
    const float* bhh2 = (const float*)d_in[8];
    float* out = (float*)d_out;
    (void)in_sizes; (void)n_in; (void)out_size;

    void *pre1, *h1, *pre2, *w1p, *w2p, *whh1T, *whh2T, *b1, *b2;
    cudaGetSymbolAddress(&pre1,  g_pre1);
    cudaGetSymbolAddress(&h1,    g_h1);
    cudaGetSymbolAddress(&pre2,  g_pre2);
    cudaGetSymbolAddress(&w1p,   g_w1p);
    cudaGetSymbolAddress(&w2p,   g_w2p);
    cudaGetSymbolAddress(&whh1T, g_whh1T);
    cudaGetSymbolAddress(&whh2T, g_whh2T);
    cudaGetSymbolAddress(&b1,    g_b1);
    cudaGetSymbolAddress(&b2,    g_b2);

    const int SMEM_G1 = IN1 * 52 * 8 + 128 * IN1 * 4;                    //  74240
    const int SMEM_G2 = NH1 * 52 * 8 + 128 * NH1 * 4;                    //  92800
    const int SMEM_L1 = NH1 * NG1 * 4 + 4 * 8 * NG1 * 4 + NH1 * 12 * 4;  // 216000
    const int SMEM_L2 = NH2 * NG2 * 4 + 2 * 8 * NG2 * 4 + NH2 * 12 * 4;  //  55200

    cudaFuncSetAttribute(gemm_kernel<IN1, NG1, 416>, cudaFuncAttributeMaxDynamicSharedMemorySize, SMEM_G1);
    cudaFuncSetAttribute(gemm_kernel<NH1, NG2, 208>, cudaFuncAttributeMaxDynamicSharedMemorySize, SMEM_G2);
    cudaFuncSetAttribute(lstm_kernel<NH1, 4, 4, false>, cudaFuncAttributeMaxDynamicSharedMemorySize, SMEM_L1);
    cudaFuncSetAttribute(lstm_kernel<NH2, 2, 2, true>,  cudaFuncAttributeMaxDynamicSharedMemorySize, SMEM_L2);

    prep_kernel<<<96, 256>>>(Wih1, Whh1, bih1, bhh1, Wih2, Whh2, bih2, bhh2);

    gemm_kernel<IN1, NG1, 416><<<dim3(BB * TT / 128, 4), 416, SMEM_G1>>>(
        x, (const float*)w1p, (const float*)b1, (float*)pre1);

    lstm_kernel<NH1, 4, 4, false><<<BB / 8, 416, SMEM_L1>>>(
        (const float*)pre1, (const float*)whh1T, (float*)h1);

    gemm_kernel<NH1, NG2, 208><<<dim3(BB * TT / 128, 2), 416, SMEM_G2>>>(
        (const float*)h1, (const float*)w2p, (const float*)b2, (float*)pre2);

    lstm_kernel<NH2, 2, 2, true><<<BB / 8, 224, SMEM_L2>>>(
        (const float*)pre2, (const float*)whh2T, out);
}

// round 7
// speedup vs baseline: 1.7254x; 1.7254x over previous
#include <cuda_runtime.h>

// ---------------------------------------------------------------------------
// Problem constants
// ---------------------------------------------------------------------------
#define TT   512
#define BB   1024
#define IN1  80
#define NH1  100
#define NG1  400
#define NH2  50
#define NG2  200

typedef unsigned long long ull;

// ---------------------------------------------------------------------------
// Device scratch
// ---------------------------------------------------------------------------
__device__ __align__(16) float g_pre1[(size_t)BB * TT * NG1];   // [b][t][400]
__device__ __align__(16) float g_h1  [(size_t)BB * TT * NH1];   // [b][t][100]
__device__ __align__(16) float g_pre2[(size_t)BB * TT * NG2];   // [b][t][200]

// MMA frag-ordered weights (bf16 hi/lo splits), layout [panel][kt][n8][lane]
__device__ __align__(16) ull g_w1fh[2 * 5 * 25 * 32];   // gemm1 hi
__device__ __align__(16) ull g_w1fl[2 * 5 * 25 * 32];   // gemm1 lo
__device__ __align__(16) ull g_w2fh[7 * 25 * 32];       // gemm2 hi (K padded 112)
__device__ __align__(16) ull g_w2fl[7 * 25 * 32];       // gemm2 lo
// LSTM recurrent weights: plain [k][g]
__device__ __align__(16) float g_whh1T[NH1 * NG1];
__device__ __align__(16) float g_whh2T[NH2 * NG2];
// Fused biases, zero-padded
__device__ __align__(16) float g_b1[512];
__device__ __align__(16) float g_b2[512];

// ---------------------------------------------------------------------------
// helpers
// ---------------------------------------------------------------------------
__device__ __forceinline__ ull ffma2(ull d, ull a, ull b) {
    asm("fma.rn.f32x2 %0, %1, %2, %0;" : "+l"(d) : "l"(a), "l"(b));
    return d;
}
__device__ __forceinline__ ull dup2(float x) {
    ull r; unsigned u = __float_as_uint(x);
    asm("mov.b64 %0, {%1, %1};" : "=l"(r) : "r"(u));
    return r;
}
__device__ __forceinline__ ull pk(float x, float y) {
    ull r;
    asm("mov.b64 %0, {%1, %2};" : "=l"(r) : "f"(x), "f"(y));
    return r;
}
// pack two f32 into bf16x2: first arg -> UPPER half, second -> LOWER half
__device__ __forceinline__ unsigned pkbf(float hi_elem, float lo_elem) {
    unsigned r;
    asm("cvt.rn.bf16x2.f32 %0, %1, %2;" : "=r"(r) : "f"(hi_elem), "f"(lo_elem));
    return r;
}
__device__ __forceinline__ float bflo_f(unsigned p) { return __uint_as_float(p << 16); }
__device__ __forceinline__ float bfhi_f(unsigned p) { return __uint_as_float(p & 0xffff0000u); }

// m16n8k16 row.col bf16 MMA, fp32 accumulate
__device__ __forceinline__ void mma16816(float& c0, float& c1, float& c2, float& c3,
                                         const unsigned* a, unsigned b0, unsigned b1) {
    asm volatile(
        "mma.sync.aligned.m16n8k16.row.col.f32.bf16.bf16.f32 "
        "{%0,%1,%2,%3}, {%4,%5,%6,%7}, {%8,%9}, {%0,%1,%2,%3};"
        : "+f"(c0), "+f"(c1), "+f"(c2), "+f"(c3)
        : "r"(a[0]), "r"(a[1]), "r"(a[2]), "r"(a[3]), "r"(b0), "r"(b1));
}

// Accurate fast activations (~1e-6 rel; NOT tanh.approx)
__device__ __forceinline__ float sigm(float x) {
    return __fdividef(1.0f, 1.0f + __expf(-x));
}
__device__ __forceinline__ float tanh_f(float x) {
    return __fdividef(2.0f, 1.0f + __expf(-2.0f * x)) - 1.0f;
}

// ---------------------------------------------------------------------------
// prep: build frag-ordered bf16 hi/lo weights, LSTM weights, biases
// ---------------------------------------------------------------------------
__global__ void prep_kernel(const float* __restrict__ Wih1, const float* __restrict__ Whh1,
                            const float* __restrict__ bih1, const float* __restrict__ bhh1,
                            const float* __restrict__ Wih2, const float* __restrict__ Whh2,
                            const float* __restrict__ bih2, const float* __restrict__ bhh2) {
    int tid = blockIdx.x * blockDim.x + threadIdx.x;
    int stride = gridDim.x * blockDim.x;

    // gemm1 frags: [p(2)][kt(5)][nt(25)][lane(32)], n=(p*25+nt)*8+l/4, k0=16kt+2(l&3)
    for (int i = tid; i < 2 * 5 * 25 * 32; i += stride) {
        int l = i & 31, t = i >> 5;
        int nt = t % 25; t /= 25;
        int kt = t % 5;  int p = t / 5;
        int n  = (p * 25 + nt) * 8 + (l >> 2);
        int k0 = 16 * kt + 2 * (l & 3);
        float w0 = Wih1[n * IN1 + k0];
        float w1 = Wih1[n * IN1 + k0 + 1];
        float w2 = Wih1[n * IN1 + k0 + 8];
        float w3 = Wih1[n * IN1 + k0 + 9];
        unsigned h0 = pkbf(w1, w0), h1 = pkbf(w3, w2);
        unsigned l0 = pkbf(w1 - bfhi_f(h0), w0 - bflo_f(h0));
        unsigned l1 = pkbf(w3 - bfhi_f(h1), w2 - bflo_f(h1));
        g_w1fh[i] = (ull)h0 | ((ull)h1 << 32);
        g_w1fl[i] = (ull)l0 | ((ull)l1 << 32);
    }
    // gemm2 frags: [kt(7)][nt(25)][lane(32)], K real 100, padded to 112
    for (int i = tid; i < 7 * 25 * 32; i += stride) {
        int l = i & 31, t = i >> 5;
        int nt = t % 25;
        int kt = t / 25;
        int n  = nt * 8 + (l >> 2);
        int k0 = 16 * kt + 2 * (l & 3);
        float w0 = (k0     < NH1) ? Wih2[n * NH1 + k0]     : 0.0f;
        float w1 = (k0 + 1 < NH1) ? Wih2[n * NH1 + k0 + 1] : 0.0f;
        float w2 = (k0 + 8 < NH1) ? Wih2[n * NH1 + k0 + 8] : 0.0f;
        float w3 = (k0 + 9 < NH1) ? Wih2[n * NH1 + k0 + 9] : 0.0f;
        unsigned h0 = pkbf(w1, w0), h1 = pkbf(w3, w2);
        unsigned l0 = pkbf(w1 - bfhi_f(h0), w0 - bflo_f(h0));
        unsigned l1 = pkbf(w3 - bfhi_f(h1), w2 - bflo_f(h1));
        g_w2fh[i] = (ull)h0 | ((ull)h1 << 32);
        g_w2fl[i] = (ull)l0 | ((ull)l1 << 32);
    }
    for (int i = tid; i < NH1 * NG1; i += stride) { int k = i / NG1, g = i % NG1; g_whh1T[i] = Whh1[g * NH1 + k]; }
    for (int i = tid; i < NH2 * NG2; i += stride) { int k = i / NG2, g = i % NG2; g_whh2T[i] = Whh2[g * NH2 + k]; }
    for (int i = tid; i < 512; i += stride) {
        g_b1[i] = (i < NG1) ? bih1[i] + bhh1[i] : 0.0f;
        g_b2[i] = (i < NG2) ? bih2[i] + bhh2[i] : 0.0f;
    }
}

// ---------------------------------------------------------------------------
// Tensor-core GEMM: out[m][G] = x[m][KREAL] @ W^T + b  via bf16 3-term split.
// CTA: 256 thr / 8 warps; M-tile 128 (warp = m16 strip); blockIdx.y = N panel.
// A frags built from gmem once (regs, all KT steps); B frags: 2 LDS.64 + 3 MMA
// per (n8, kstep). Error ~2^-17 per product, fp32 accumulate.
// ---------------------------------------------------------------------------
template<int KT, int NTP, int KREAL, int G>
__global__ __launch_bounds__(256, 2)
void mma_gemm(const float* __restrict__ x, const ull* __restrict__ wfh,
              const ull* __restrict__ wfl, const float* __restrict__ bias,
              float* __restrict__ out) {
    constexpr int K = KT * 16;
    constexpr int NFRAG = KT * NTP * 32;
    extern __shared__ ull smw[];
    ull* shi = smw;
    ull* slo = smw + NFRAG;

    int tid  = threadIdx.x;
    int lane = tid & 31;
    int wi   = tid >> 5;
    int m0   = blockIdx.x * 128;
    int pb   = blockIdx.y;

    const ull* srch = wfh + (size_t)pb * NFRAG;
    const ull* srcl = wfl + (size_t)pb * NFRAG;
    for (int i = tid; i < NFRAG; i += 256) { shi[i] = srch[i]; slo[i] = srcl[i]; }
    __syncthreads();

    int r0 = m0 + wi * 16 + (lane >> 2);
    int r1 = r0 + 8;
    int cb = 2 * (lane & 3);

    // A fragments: hi/lo splits, kept in registers for all K steps
    unsigned ahi[KT][4], alo[KT][4];
#pragma unroll
    for (int kt = 0; kt < KT; kt++) {
#pragma unroll
        for (int q = 0; q < 4; q++) {
            int rr = (q & 1) ? r1 : r0;
            int cc = 16 * kt + cb + (q >> 1) * 8;
            float2 v = make_float2(0.0f, 0.0f);
            if (K == KREAL || cc + 2 <= KREAL)
                v = *(const float2*)(x + (size_t)rr * KREAL + cc);
            unsigned h = pkbf(v.y, v.x);
            ahi[kt][q] = h;
            alo[kt][q] = pkbf(v.y - bfhi_f(h), v.x - bflo_f(h));
        }
    }

    for (int nt = 0; nt < NTP; nt++) {
        int ng = (pb * NTP + nt) * 8 + cb;
        float2 bv = *(const float2*)(bias + ng);
        float c0 = bv.x, c1 = bv.y, c2 = bv.x, c3 = bv.y;
        const ull* ph = shi + nt * 32 + lane;
        const ull* pl = slo + nt * 32 + lane;
#pragma unroll
        for (int kt = 0; kt < KT; kt++) {
            ull bh = ph[kt * NTP * 32];
            ull bl = pl[kt * NTP * 32];
            unsigned bh0 = (unsigned)bh, bh1 = (unsigned)(bh >> 32);
            unsigned bl0 = (unsigned)bl, bl1 = (unsigned)(bl >> 32);
            mma16816(c0, c1, c2, c3, ahi[kt], bl0, bl1);   // hi * lo
            mma16816(c0, c1, c2, c3, alo[kt], bh0, bh1);   // lo * hi
            mma16816(c0, c1, c2, c3, ahi[kt], bh0, bh1);   // hi * hi
        }
        *(float2*)(out + (size_t)r0 * G + ng) = make_float2(c0, c1);
        *(float2*)(out + (size_t)r1 * G + ng) = make_float2(c2, c3);
    }
}

// ---------------------------------------------------------------------------
// Persistent LSTM (round-4 configuration — best measured).
// 8 batch rows/CTA, 128 CTAs. Gate phase (tid<200): rows 4rg..4rg+3, PPT cols;
// row-pair packed FFMA2. Update phase: UPT units/thread, c in registers.
// ---------------------------------------------------------------------------
template<int H, int PPT, bool LAST_ONLY>
__global__ __launch_bounds__(224, 1)
void lstm_kernel(const float* __restrict__ pre, const float* __restrict__ whhT,
                 float* __restrict__ hout) {
    constexpr int G    = 4 * H;
    constexpr int NCG  = G / PPT;          // 100 for both layers
    constexpr int NACT = 2 * NCG;          // 200
    constexpr int UPT  = 8 * H / NACT;     // 4 (H=100) / 2 (H=50)
    constexpr int RP   = 10;               // padded row-slot dim

    extern __shared__ float sm[];
    float* sw  = sm;                       // [H][G] recurrent weights
    float* sgt = sm + H * G;               // [G][RP] gate staging (transposed)
    float* shp = sgt + G * RP;             // [H][RP] h (row-packed)

    int tid = threadIdx.x;
    int b0  = blockIdx.x * 8;

    for (int i = tid; i < H * G; i += blockDim.x) sw[i] = whhT[i];
    for (int i = tid; i < H * RP; i += blockDim.x) shp[i] = 0.0f;
    __syncthreads();

    bool gate = (tid < NACT);
    int rg = 0, cg = 0;
    if (gate) { rg = tid / NCG; cg = tid - rg * NCG; }
    int r0 = 4 * rg;
    int c0 = PPT * cg;

    int ur[UPT], uj[UPT];
#pragma unroll
    for (int i = 0; i < UPT; i++) {
        int u = tid + i * NACT;
        ur[i] = u / H; uj[i] = u - ur[i] * H;
    }
    float cst[UPT];
#pragma unroll
    for (int i = 0; i < UPT; i++) cst[i] = 0.0f;

    float pv[4][PPT];
    if (gate) {
#pragma unroll
        for (int r = 0; r < 4; r++) {
            const float* src = pre + ((size_t)(b0 + r0 + r) * TT) * G + c0;
            if (PPT == 4) { float4 v = *(const float4*)src; pv[r][0]=v.x; pv[r][1]=v.y; pv[r][2]=v.z; pv[r][3]=v.w; }
            else          { float2 v = *(const float2*)src; pv[r][0]=v.x; pv[r][1]=v.y; }
        }
    }

    for (int t = 0; t < TT; t++) {
        if (gate) {
            ull acc[2][PPT];
#pragma unroll
            for (int j = 0; j < PPT; j++) {
                acc[0][j] = pk(pv[0][j], pv[1][j]);
                acc[1][j] = pk(pv[2][j], pv[3][j]);
            }
            int tn = (t + 1 < TT) ? t + 1 : t;
#pragma unroll
            for (int r = 0; r < 4; r++) {
                const float* src = pre + ((size_t)(b0 + r0 + r) * TT + tn) * G + c0;
                if (PPT == 4) { float4 v = *(const float4*)src; pv[r][0]=v.x; pv[r][1]=v.y; pv[r][2]=v.z; pv[r][3]=v.w; }
                else          { float2 v = *(const float2*)src; pv[r][0]=v.x; pv[r][1]=v.y; }
            }

#pragma unroll 4
            for (int k = 0; k < H; k++) {
                ull hA = *(const ull*)(shp + k * RP + r0);       // rows r0,r0+1
                ull hB = *(const ull*)(shp + k * RP + r0 + 2);   // rows r0+2,r0+3
                const float* wr = sw + k * G + c0;
                float wf[PPT];
                if (PPT == 4) { float4 v = *(const float4*)wr; wf[0]=v.x; wf[1]=v.y; wf[2]=v.z; wf[3]=v.w; }
                else          { float2 v = *(const float2*)wr; wf[0]=v.x; wf[1]=v.y; }
#pragma unroll
                for (int j = 0; j < PPT; j++) {
                    ull wd = dup2(wf[j]);
                    acc[0][j] = ffma2(acc[0][j], hA, wd);
                    acc[1][j] = ffma2(acc[1][j], hB, wd);
                }
            }
#pragma unroll
            for (int j = 0; j < PPT; j++) {
                *(ull*)(sgt + (c0 + j) * RP + r0)     = acc[0][j];
                *(ull*)(sgt + (c0 + j) * RP + r0 + 2) = acc[1][j];
            }
        }
        __syncthreads();

        if (tid < NACT) {
#pragma unroll
            for (int i = 0; i < UPT; i++) {
                int r = ur[i], j = uj[i];
                float ig = sigm(sgt[(0 * H + j) * RP + r]);
                float fg = sigm(sgt[(1 * H + j) * RP + r]);
                float gg = tanh_f(sgt[(2 * H + j) * RP + r]);
                float og = sigm(sgt[(3 * H + j) * RP + r]);
                float c  = fg * cst[i] + ig * gg;
                cst[i] = c;
                float h  = og * tanh_f(c);
                shp[j * RP + r] = h;
                if (!LAST_ONLY) {
                    hout[((size_t)(b0 + r) * TT + t) * H + j] = h;
                } else if (t == TT - 1) {
                    hout[(size_t)(b0 + r) * H + j] = h;
                }
            }
        }
        __syncthreads();
    }
}

// ---------------------------------------------------------------------------
// Launch
// ---------------------------------------------------------------------------
extern "C" void kernel_launch(void* const* d_in, const int* in_sizes, int n_in,
                              void* d_out, int out_size) {
    const float* x    = (const float*)d_in[0];
    const float* Wih1 = (const float*)d_in[1];
    const float* Whh1 = (const float*)d_in[2];
    const float* bih1 = (const float*)d_in[3];
    const float* bhh1 = (const float*)d_in[4];
    const float* Wih2 = (const float*)d_in[5];
    const float* Whh2 = (const float*)d_in[6];
    const float* bih2 = (const float*)d_in[7];
    const float* bhh2 = (const float*)d_in[8];
    float* out = (float*)d_out;
    (void)in_sizes; (void)n_in; (void)out_size;

    void *pre1, *h1, *pre2, *w1fh, *w1fl, *w2fh, *w2fl, *whh1T, *whh2T, *b1, *b2;
    cudaGetSymbolAddress(&pre1,  g_pre1);
    cudaGetSymbolAddress(&h1,    g_h1);
    cudaGetSymbolAddress(&pre2,  g_pre2);
    cudaGetSymbolAddress(&w1fh,  g_w1fh);
    cudaGetSymbolAddress(&w1fl,  g_w1fl);
    cudaGetSymbolAddress(&w2fh,  g_w2fh);
    cudaGetSymbolAddress(&w2fl,  g_w2fl);
    cudaGetSymbolAddress(&whh1T, g_whh1T);
    cudaGetSymbolAddress(&whh2T, g_whh2T);
    cudaGetSymbolAddress(&b1,    g_b1);
    cudaGetSymbolAddress(&b2,    g_b2);

    const int SMEM_G1 = 2 * 5 * 25 * 32 * 8;                         //  64000
    const int SMEM_G2 = 2 * 7 * 25 * 32 * 8;                         //  89600
    const int SMEM_L1 = NH1 * NG1 * 4 + NG1 * 10 * 4 + NH1 * 10 * 4; // 180000
    const int SMEM_L2 = NH2 * NG2 * 4 + NG2 * 10 * 4 + NH2 * 10 * 4; //  50000

    cudaFuncSetAttribute(mma_gemm<5, 25, IN1, NG1>, cudaFuncAttributeMaxDynamicSharedMemorySize, SMEM_G1);
    cudaFuncSetAttribute(mma_gemm<7, 25, NH1, NG2>, cudaFuncAttributeMaxDynamicSharedMemorySize, SMEM_G2);
    cudaFuncSetAttribute(lstm_kernel<NH1, 4, false>, cudaFuncAttributeMaxDynamicSharedMemorySize, SMEM_L1);
    cudaFuncSetAttribute(lstm_kernel<NH2, 2, true>,  cudaFuncAttributeMaxDynamicSharedMemorySize, SMEM_L2);

    prep_kernel<<<96, 256>>>(Wih1, Whh1, bih1, bhh1, Wih2, Whh2, bih2, bhh2);

    mma_gemm<5, 25, IN1, NG1><<<dim3(BB * TT / 128, 2), 256, SMEM_G1>>>(
        x, (const ull*)w1fh, (const ull*)w1fl, (const float*)b1, (float*)pre1);

    lstm_kernel<NH1, 4, false><<<BB / 8, 224, SMEM_L1>>>(
        (const float*)pre1, (const float*)whh1T, (float*)h1);

    mma_gemm<7, 25, NH1, NG2><<<dim3(BB * TT / 128, 1), 256, SMEM_G2>>>(
        (const float*)h1, (const ull*)w2fh, (const ull*)w2fl, (const float*)b2, (float*)pre2);

    lstm_kernel<NH2, 2, true><<<BB / 8, 224, SMEM_L2>>>(
        (const float*)pre2, (const float*)whh2T, out);
}

// round 9
// speedup vs baseline: 1.9250x; 1.1157x over previous
#include <cuda_runtime.h>

// ---------------------------------------------------------------------------
// Problem constants
// ---------------------------------------------------------------------------
#define TT   512
#define BB   1024
#define IN1  80
#define NH1  100
#define NG1  400
#define NH2  50
#define NG2  200

typedef unsigned long long ull;

// ---------------------------------------------------------------------------
// Device scratch
// ---------------------------------------------------------------------------
__device__ __align__(16) float g_pre1[(size_t)BB * TT * NG1];   // [b][t][400]
__device__ __align__(16) float g_h1  [(size_t)BB * TT * NH1];   // [b][t][100]
__device__ __align__(16) float g_pre2[(size_t)BB * TT * NG2];   // [b][t][200]

// MMA frag-ordered weights (bf16 hi/lo splits), layout [panel][kt][n8][lane]
__device__ __align__(16) ull g_w1fh[2 * 5 * 25 * 32];   // gemm1 hi
__device__ __align__(16) ull g_w1fl[2 * 5 * 25 * 32];   // gemm1 lo
__device__ __align__(16) ull g_w2fh[7 * 25 * 32];       // gemm2 hi (K padded 112)
__device__ __align__(16) ull g_w2fl[7 * 25 * 32];       // gemm2 lo
// LSTM recurrent weights: plain [k][g]
__device__ __align__(16) float g_whh1T[NH1 * NG1];
__device__ __align__(16) float g_whh2T[NH2 * NG2];
// Fused biases, zero-padded
__device__ __align__(16) float g_b1[512];
__device__ __align__(16) float g_b2[512];

// ---------------------------------------------------------------------------
// helpers
// ---------------------------------------------------------------------------
__device__ __forceinline__ ull ffma2(ull d, ull a, ull b) {
    asm("fma.rn.f32x2 %0, %1, %2, %0;" : "+l"(d) : "l"(a), "l"(b));
    return d;
}
__device__ __forceinline__ ull dup2(float x) {
    ull r; unsigned u = __float_as_uint(x);
    asm("mov.b64 %0, {%1, %1};" : "=l"(r) : "r"(u));
    return r;
}
__device__ __forceinline__ ull pk(float x, float y) {
    ull r;
    asm("mov.b64 %0, {%1, %2};" : "=l"(r) : "f"(x), "f"(y));
    return r;
}
__device__ __forceinline__ void upk(ull v, float& a, float& b) {
    unsigned lo, hi;
    asm("mov.b64 {%0, %1}, %2;" : "=r"(lo), "=r"(hi) : "l"(v));
    a = __uint_as_float(lo); b = __uint_as_float(hi);
}
// pack two f32 into bf16x2: first arg -> UPPER half, second -> LOWER half
__device__ __forceinline__ unsigned pkbf(float hi_elem, float lo_elem) {
    unsigned r;
    asm("cvt.rn.bf16x2.f32 %0, %1, %2;" : "=r"(r) : "f"(hi_elem), "f"(lo_elem));
    return r;
}
__device__ __forceinline__ float bflo_f(unsigned p) { return __uint_as_float(p << 16); }
__device__ __forceinline__ float bfhi_f(unsigned p) { return __uint_as_float(p & 0xffff0000u); }

// m16n8k16 row.col bf16 MMA, fp32 accumulate
__device__ __forceinline__ void mma16816(float& c0, float& c1, float& c2, float& c3,
                                         const unsigned* a, unsigned b0, unsigned b1) {
    asm volatile(
        "mma.sync.aligned.m16n8k16.row.col.f32.bf16.bf16.f32 "
        "{%0,%1,%2,%3}, {%4,%5,%6,%7}, {%8,%9}, {%0,%1,%2,%3};"
        : "+f"(c0), "+f"(c1), "+f"(c2), "+f"(c3)
        : "r"(a[0]), "r"(a[1]), "r"(a[2]), "r"(a[3]), "r"(b0), "r"(b1));
}

// MUFU-based activations (tanh.approx: 1 MUFU, ~2^-11 abs err)
__device__ __forceinline__ float tanh_m(float x) {
    float r; asm("tanh.approx.f32 %0, %1;" : "=f"(r) : "f"(x));
    return r;
}
__device__ __forceinline__ float sigm_m(float x) {
    return fmaf(0.5f, tanh_m(0.5f * x), 0.5f);
}

// ---------------------------------------------------------------------------
// prep: build frag-ordered bf16 hi/lo weights, LSTM weights, biases
// ---------------------------------------------------------------------------
__global__ void prep_kernel(const float* __restrict__ Wih1, const float* __restrict__ Whh1,
                            const float* __restrict__ bih1, const float* __restrict__ bhh1,
                            const float* __restrict__ Wih2, const float* __restrict__ Whh2,
                            const float* __restrict__ bih2, const float* __restrict__ bhh2) {
    int tid = blockIdx.x * blockDim.x + threadIdx.x;
    int stride = gridDim.x * blockDim.x;

    for (int i = tid; i < 2 * 5 * 25 * 32; i += stride) {
        int l = i & 31, t = i >> 5;
        int nt = t % 25; t /= 25;
        int kt = t % 5;  int p = t / 5;
        int n  = (p * 25 + nt) * 8 + (l >> 2);
        int k0 = 16 * kt + 2 * (l & 3);
        float w0 = Wih1[n * IN1 + k0];
        float w1 = Wih1[n * IN1 + k0 + 1];
        float w2 = Wih1[n * IN1 + k0 + 8];
        float w3 = Wih1[n * IN1 + k0 + 9];
        unsigned h0 = pkbf(w1, w0), h1 = pkbf(w3, w2);
        unsigned l0 = pkbf(w1 - bfhi_f(h0), w0 - bflo_f(h0));
        unsigned l1 = pkbf(w3 - bfhi_f(h1), w2 - bflo_f(h1));
        g_w1fh[i] = (ull)h0 | ((ull)h1 << 32);
        g_w1fl[i] = (ull)l0 | ((ull)l1 << 32);
    }
    for (int i = tid; i < 7 * 25 * 32; i += stride) {
        int l = i & 31, t = i >> 5;
        int nt = t % 25;
        int kt = t / 25;
        int n  = nt * 8 + (l >> 2);
        int k0 = 16 * kt + 2 * (l & 3);
        float w0 = (k0     < NH1) ? Wih2[n * NH1 + k0]     : 0.0f;
        float w1 = (k0 + 1 < NH1) ? Wih2[n * NH1 + k0 + 1] : 0.0f;
        float w2 = (k0 + 8 < NH1) ? Wih2[n * NH1 + k0 + 8] : 0.0f;
        float w3 = (k0 + 9 < NH1) ? Wih2[n * NH1 + k0 + 9] : 0.0f;
        unsigned h0 = pkbf(w1, w0), h1 = pkbf(w3, w2);
        unsigned l0 = pkbf(w1 - bfhi_f(h0), w0 - bflo_f(h0));
        unsigned l1 = pkbf(w3 - bfhi_f(h1), w2 - bflo_f(h1));
        g_w2fh[i] = (ull)h0 | ((ull)h1 << 32);
        g_w2fl[i] = (ull)l0 | ((ull)l1 << 32);
    }
    for (int i = tid; i < NH1 * NG1; i += stride) { int k = i / NG1, g = i % NG1; g_whh1T[i] = Whh1[g * NH1 + k]; }
    for (int i = tid; i < NH2 * NG2; i += stride) { int k = i / NG2, g = i % NG2; g_whh2T[i] = Whh2[g * NH2 + k]; }
    for (int i = tid; i < 512; i += stride) {
        g_b1[i] = (i < NG1) ? bih1[i] + bhh1[i] : 0.0f;
        g_b2[i] = (i < NG2) ? bih2[i] + bhh2[i] : 0.0f;
    }
}

// ---------------------------------------------------------------------------
// Tensor-core GEMM (unchanged from round 7 — measured 211us / tensor 55%).
// ---------------------------------------------------------------------------
template<int KT, int NTP, int KREAL, int G>
__global__ __launch_bounds__(256, 2)
void mma_gemm(const float* __restrict__ x, const ull* __restrict__ wfh,
              const ull* __restrict__ wfl, const float* __restrict__ bias,
              float* __restrict__ out) {
    constexpr int K = KT * 16;
    constexpr int NFRAG = KT * NTP * 32;
    extern __shared__ ull smw[];
    ull* shi = smw;
    ull* slo = smw + NFRAG;

    int tid  = threadIdx.x;
    int lane = tid & 31;
    int wi   = tid >> 5;
    int m0   = blockIdx.x * 128;
    int pb   = blockIdx.y;

    const ull* srch = wfh + (size_t)pb * NFRAG;
    const ull* srcl = wfl + (size_t)pb * NFRAG;
    for (int i = tid; i < NFRAG; i += 256) { shi[i] = srch[i]; slo[i] = srcl[i]; }
    __syncthreads();

    int r0 = m0 + wi * 16 + (lane >> 2);
    int r1 = r0 + 8;
    int cb = 2 * (lane & 3);

    unsigned ahi[KT][4], alo[KT][4];
#pragma unroll
    for (int kt = 0; kt < KT; kt++) {
#pragma unroll
        for (int q = 0; q < 4; q++) {
            int rr = (q & 1) ? r1 : r0;
            int cc = 16 * kt + cb + (q >> 1) * 8;
            float2 v = make_float2(0.0f, 0.0f);
            if (K == KREAL || cc + 2 <= KREAL)
                v = *(const float2*)(x + (size_t)rr * KREAL + cc);
            unsigned h = pkbf(v.y, v.x);
            ahi[kt][q] = h;
            alo[kt][q] = pkbf(v.y - bfhi_f(h), v.x - bflo_f(h));
        }
    }

    for (int nt = 0; nt < NTP; nt++) {
        int ng = (pb * NTP + nt) * 8 + cb;
        float2 bv = *(const float2*)(bias + ng);
        float c0 = bv.x, c1 = bv.y, c2 = bv.x, c3 = bv.y;
        const ull* ph = shi + nt * 32 + lane;
        const ull* pl = slo + nt * 32 + lane;
#pragma unroll
        for (int kt = 0; kt < KT; kt++) {
            ull bh = ph[kt * NTP * 32];
            ull bl = pl[kt * NTP * 32];
            unsigned bh0 = (unsigned)bh, bh1 = (unsigned)(bh >> 32);
            unsigned bl0 = (unsigned)bl, bl1 = (unsigned)(bl >> 32);
            mma16816(c0, c1, c2, c3, ahi[kt], bl0, bl1);   // hi * lo
            mma16816(c0, c1, c2, c3, alo[kt], bh0, bh1);   // lo * hi
            mma16816(c0, c1, c2, c3, ahi[kt], bh0, bh1);   // hi * hi
        }
        *(float2*)(out + (size_t)r0 * G + ng) = make_float2(c0, c1);
        *(float2*)(out + (size_t)r1 * G + ng) = make_float2(c2, c3);
    }
}

// ---------------------------------------------------------------------------
// Persistent LSTM v2: 8 batch rows/CTA, 128 CTAs.
// Gate phase: NACT=200 threads; RSP=1 (H=100): thread = all 8 rows x 2 cols;
//   RSP=2 (H=50): thread = 4 rows x 2 cols. Per k: broadcast LDS.128 h (shp
//   [k][12], 16B-aligned) + coalesced LDS.64 w + 2 dup + 8/4 FFMA2.
// Staging store: even column as ull (index provably 8B-aligned), odd column
//   unpacked as 2x STS.32 (RPS=13 is odd -> odd columns are only 4B-aligned).
// Update: MUFU tanh.approx activations (4 MUFU/unit vs 10).
// ---------------------------------------------------------------------------
template<int H, int RSP, bool LAST_ONLY>
__global__ __launch_bounds__(224, 1)
void lstm_kernel(const float* __restrict__ pre, const float* __restrict__ whhT,
                 float* __restrict__ hout) {
    constexpr int G    = 4 * H;
    constexpr int NCG  = G / 2;            // col-threads per row-group
    constexpr int NACT = RSP * NCG;        // 200 for both layers
    constexpr int RPT  = 8 / RSP;          // rows per thread (8 / 4)
    constexpr int NQ   = RPT / 2;          // row-pairs per thread (4 / 2)
    constexpr int UPT  = 8 * H / NACT;     // update units per thread (4 / 2)
    constexpr int RPS  = 13;               // sgt row pad (conflict-free update)
    constexpr int RPH  = 12;               // shp row pad (16B-aligned rows)

    extern __shared__ float sm[];
    float* sw  = sm;                       // [H][G] recurrent weights
    float* sgt = sm + H * G;               // [G][13] gate staging (col-major)
    float* shp = sgt + G * RPS;            // [H][12] h (rows packed)

    int tid = threadIdx.x;
    int b0  = blockIdx.x * 8;

    for (int i = tid; i < H * G; i += blockDim.x) sw[i] = whhT[i];
    for (int i = tid; i < H * RPH; i += blockDim.x) shp[i] = 0.0f;
    __syncthreads();

    bool gate = (tid < NACT);
    int rg = 0, cg = 0;
    if (gate) { rg = tid / NCG; cg = tid - rg * NCG; }
    int r0 = rg * RPT;
    int c0 = 2 * cg;

    int ur[UPT], uj[UPT];
#pragma unroll
    for (int i = 0; i < UPT; i++) {
        int u = tid + i * NACT;
        ur[i] = u / H; uj[i] = u - ur[i] * H;
    }
    float cst[UPT];
#pragma unroll
    for (int i = 0; i < UPT; i++) cst[i] = 0.0f;

    // prefetched pre: rows r0..r0+RPT-1, cols c0,c0+1
    float pv[RPT][2];
    if (gate) {
#pragma unroll
        for (int r = 0; r < RPT; r++) {
            float2 v = *(const float2*)(pre + ((size_t)(b0 + r0 + r) * TT) * G + c0);
            pv[r][0] = v.x; pv[r][1] = v.y;
        }
    }

    for (int t = 0; t < TT; t++) {
        if (gate) {
            ull acc[NQ][2];
#pragma unroll
            for (int q = 0; q < NQ; q++) {
                acc[q][0] = pk(pv[2 * q][0], pv[2 * q + 1][0]);
                acc[q][1] = pk(pv[2 * q][1], pv[2 * q + 1][1]);
            }
            int tn = (t + 1 < TT) ? t + 1 : t;
#pragma unroll
            for (int r = 0; r < RPT; r++) {
                float2 v = *(const float2*)(pre + ((size_t)(b0 + r0 + r) * TT + tn) * G + c0);
                pv[r][0] = v.x; pv[r][1] = v.y;
            }

#pragma unroll 4
            for (int k = 0; k < H; k++) {
                const float* hp = shp + k * RPH + r0;
                float2 w = *(const float2*)(sw + k * G + c0);
                ull w0 = dup2(w.x), w1 = dup2(w.y);
                if (RPT == 8) {
                    ulonglong2 hA = *(const ulonglong2*)(hp);       // rows 0-3
                    ulonglong2 hB = *(const ulonglong2*)(hp + 4);   // rows 4-7
                    acc[0][0] = ffma2(acc[0][0], hA.x, w0); acc[0][1] = ffma2(acc[0][1], hA.x, w1);
                    acc[1][0] = ffma2(acc[1][0], hA.y, w0); acc[1][1] = ffma2(acc[1][1], hA.y, w1);
                    acc[2][0] = ffma2(acc[2][0], hB.x, w0); acc[2][1] = ffma2(acc[2][1], hB.x, w1);
                    acc[3][0] = ffma2(acc[3][0], hB.y, w0); acc[3][1] = ffma2(acc[3][1], hB.y, w1);
                } else {
                    ulonglong2 hA = *(const ulonglong2*)(hp);       // 4 rows
                    acc[0][0] = ffma2(acc[0][0], hA.x, w0); acc[0][1] = ffma2(acc[0][1], hA.x, w1);
                    acc[1][0] = ffma2(acc[1][0], hA.y, w0); acc[1][1] = ffma2(acc[1][1], hA.y, w1);
                }
            }
            // even column: ull store (c0*13 + r0 + 2q is even -> 8B aligned);
            // odd column: unpacked 32-bit stores (odd*13 is odd -> 4B only)
#pragma unroll
            for (int q = 0; q < NQ; q++) {
                *(ull*)(sgt + c0 * RPS + r0 + 2 * q) = acc[q][0];
                float f0, f1; upk(acc[q][1], f0, f1);
                sgt[(c0 + 1) * RPS + r0 + 2 * q]     = f0;
                sgt[(c0 + 1) * RPS + r0 + 2 * q + 1] = f1;
            }
        }
        __syncthreads();

        if (tid < NACT) {
#pragma unroll
            for (int i = 0; i < UPT; i++) {
                int r = ur[i], j = uj[i];
                float ig = sigm_m(sgt[(0 * H + j) * RPS + r]);
                float fg = sigm_m(sgt[(1 * H + j) * RPS + r]);
                float gg = tanh_m(sgt[(2 * H + j) * RPS + r]);
                float og = sigm_m(sgt[(3 * H + j) * RPS + r]);
                float c  = fg * cst[i] + ig * gg;
                cst[i] = c;
                float h  = og * tanh_m(c);
                shp[j * RPH + r] = h;
                if (!LAST_ONLY) {
                    hout[((size_t)(b0 + r) * TT + t) * H + j] = h;
                } else if (t == TT - 1) {
                    hout[(size_t)(b0 + r) * H + j] = h;
                }
            }
        }
        __syncthreads();
    }
}

// ---------------------------------------------------------------------------
// Launch
// ---------------------------------------------------------------------------
extern "C" void kernel_launch(void* const* d_in, const int* in_sizes, int n_in,
                              void* d_out, int out_size) {
    const float* x    = (const float*)d_in[0];
    const float* Wih1 = (const float*)d_in[1];
    const float* Whh1 = (const float*)d_in[2];
    const float* bih1 = (const float*)d_in[3];
    const float* bhh1 = (const float*)d_in[4];
    const float* Wih2 = (const float*)d_in[5];
    const float* Whh2 = (const float*)d_in[6];
    const float* bih2 = (const float*)d_in[7];
    const float* bhh2 = (const float*)d_in[8];
    float* out = (float*)d_out;
    (void)in_sizes; (void)n_in; (void)out_size;

    void *pre1, *h1, *pre2, *w1fh, *w1fl, *w2fh, *w2fl, *whh1T, *whh2T, *b1, *b2;
    cudaGetSymbolAddress(&pre1,  g_pre1);
    cudaGetSymbolAddress(&h1,    g_h1);
    cudaGetSymbolAddress(&pre2,  g_pre2);
    cudaGetSymbolAddress(&w1fh,  g_w1fh);
    cudaGetSymbolAddress(&w1fl,  g_w1fl);
    cudaGetSymbolAddress(&w2fh,  g_w2fh);
    cudaGetSymbolAddress(&w2fl,  g_w2fl);
    cudaGetSymbolAddress(&whh1T, g_whh1T);
    cudaGetSymbolAddress(&whh2T, g_whh2T);
    cudaGetSymbolAddress(&b1,    g_b1);
    cudaGetSymbolAddress(&b2,    g_b2);

    const int SMEM_G1 = 2 * 5 * 25 * 32 * 8;                          //  64000
    const int SMEM_G2 = 2 * 7 * 25 * 32 * 8;                          //  89600
    const int SMEM_L1 = NH1 * NG1 * 4 + NG1 * 13 * 4 + NH1 * 12 * 4;  // 185600
    const int SMEM_L2 = NH2 * NG2 * 4 + NG2 * 13 * 4 + NH2 * 12 * 4;  //  52800

    cudaFuncSetAttribute(mma_gemm<5, 25, IN1, NG1>, cudaFuncAttributeMaxDynamicSharedMemorySize, SMEM_G1);
    cudaFuncSetAttribute(mma_gemm<7, 25, NH1, NG2>, cudaFuncAttributeMaxDynamicSharedMemorySize, SMEM_G2);
    cudaFuncSetAttribute(lstm_kernel<NH1, 1, false>, cudaFuncAttributeMaxDynamicSharedMemorySize, SMEM_L1);
    cudaFuncSetAttribute(lstm_kernel<NH2, 2, true>,  cudaFuncAttributeMaxDynamicSharedMemorySize, SMEM_L2);

    prep_kernel<<<96, 256>>>(Wih1, Whh1, bih1, bhh1, Wih2, Whh2, bih2, bhh2);

    mma_gemm<5, 25, IN1, NG1><<<dim3(BB * TT / 128, 2), 256, SMEM_G1>>>(
        x, (const ull*)w1fh, (const ull*)w1fl, (const float*)b1, (float*)pre1);

    lstm_kernel<NH1, 1, false><<<BB / 8, 224, SMEM_L1>>>(
        (const float*)pre1, (const float*)whh1T, (float*)h1);

    mma_gemm<7, 25, NH1, NG2><<<dim3(BB * TT / 128, 1), 256, SMEM_G2>>>(
        (const float*)h1, (const ull*)w2fh, (const ull*)w2fl, (const float*)b2, (float*)pre2);

    lstm_kernel<NH2, 2, true><<<BB / 8, 224, SMEM_L2>>>(
        (const float*)pre2, (const float*)whh2T, out);
}